// round 1
// baseline (speedup 1.0000x reference)
#include <cuda_runtime.h>
#include <math.h>

#define IMG_H 192
#define IMG_W 192
#define NPIX (IMG_H * IMG_W)
#define PMAX 256
#define TANFOVX 0.5f
#define TANFOVY 0.5f
#define NEAR_P 0.2f
#define ALPHA_MIN (1.0f / 255.0f)
#define T_EPS 1e-4f

// Sorted (by depth, ascending) gaussian parameters, SoA in device globals
// (no cudaMalloc allowed).
__device__ float g_px[PMAX];
__device__ float g_py[PMAX];
__device__ float g_cA[PMAX];
__device__ float g_cB[PMAX];
__device__ float g_cC[PMAX];
__device__ float g_op[PMAX];
__device__ float g_cr[PMAX];
__device__ float g_cg[PMAX];
__device__ float g_cb[PMAX];

// ---------------------------------------------------------------------------
// Kernel 1: preprocess all P gaussians (one block, P threads), bitonic-sort by
// depth in shared memory, scatter sorted params to globals, write radii output.
// ---------------------------------------------------------------------------
__global__ void preprocess_kernel(
    const float* __restrict__ means3D,     // [P,3]
    const float* __restrict__ opacities,   // [P,1]
    const float* __restrict__ colors,      // [P,3]
    const float* __restrict__ scales,      // [P,3]
    const float* __restrict__ rotations,   // [P,4]
    const float* __restrict__ viewmatrix,  // [4,4] row-major
    const float* __restrict__ projmatrix,  // [4,4] row-major
    float* __restrict__ out_radii)         // P floats (tail of d_out)
{
    const int i = threadIdx.x;

    __shared__ float s_key[PMAX];
    __shared__ int   s_idx[PMAX];
    __shared__ float s_px[PMAX], s_py[PMAX];
    __shared__ float s_cA[PMAX], s_cB[PMAX], s_cC[PMAX];
    __shared__ float s_op[PMAX];
    __shared__ float s_cr[PMAX], s_cg[PMAX], s_cb[PMAX];

    // ---- per-gaussian geometry ----
    const float mx = means3D[3 * i + 0];
    const float my = means3D[3 * i + 1];
    const float mz = means3D[3 * i + 2];
    const float* vm = viewmatrix;
    const float* pm = projmatrix;

    // p_view = m @ V[:3,:3] + V[3,:3]   (row-vector convention)
    const float pv0 = mx * vm[0] + my * vm[4] + mz * vm[8]  + vm[12];
    const float pv1 = mx * vm[1] + my * vm[5] + mz * vm[9]  + vm[13];
    const float pv2 = mx * vm[2] + my * vm[6] + mz * vm[10] + vm[14];

    // p_hom = [m,1] @ P
    const float ph0 = mx * pm[0] + my * pm[4] + mz * pm[8]  + pm[12];
    const float ph1 = mx * pm[1] + my * pm[5] + mz * pm[9]  + pm[13];
    const float ph3 = mx * pm[3] + my * pm[7] + mz * pm[11] + pm[15];
    const float inv_w = 1.0f / (ph3 + 1e-7f);
    const float pp0 = ph0 * inv_w;
    const float pp1 = ph1 * inv_w;

    const float depth = pv2;
    const bool in_frustum = depth > NEAR_P;

    // quaternion -> rotation
    float qr = rotations[4 * i + 0];
    float qx = rotations[4 * i + 1];
    float qy = rotations[4 * i + 2];
    float qz = rotations[4 * i + 3];
    {
        const float qn = rsqrtf(qr * qr + qx * qx + qy * qy + qz * qz);
        qr *= qn; qx *= qn; qy *= qn; qz *= qn;
    }
    float R[3][3];
    R[0][0] = 1.f - 2.f * (qy * qy + qz * qz);
    R[0][1] = 2.f * (qx * qy - qr * qz);
    R[0][2] = 2.f * (qx * qz + qr * qy);
    R[1][0] = 2.f * (qx * qy + qr * qz);
    R[1][1] = 1.f - 2.f * (qx * qx + qz * qz);
    R[1][2] = 2.f * (qy * qz - qr * qx);
    R[2][0] = 2.f * (qx * qz - qr * qy);
    R[2][1] = 2.f * (qy * qz + qr * qx);
    R[2][2] = 1.f - 2.f * (qx * qx + qy * qy);

    const float s0 = scales[3 * i + 0];
    const float s1 = scales[3 * i + 1];
    const float s2v = scales[3 * i + 2];
    const float w0 = s0 * s0, w1 = s1 * s1, w2 = s2v * s2v;

    // Sigma = R diag(w) R^T (symmetric 3x3)
    float S[3][3];
    #pragma unroll
    for (int a = 0; a < 3; a++)
        #pragma unroll
        for (int b = 0; b < 3; b++)
            S[a][b] = R[a][0] * w0 * R[b][0] + R[a][1] * w1 * R[b][1] + R[a][2] * w2 * R[b][2];

    const float tz = in_frustum ? depth : 1.0f;
    const float lx = 1.3f * TANFOVX, ly = 1.3f * TANFOVY;
    const float tx = fminf(fmaxf(pv0 / tz, -lx), lx) * tz;
    const float ty = fminf(fmaxf(pv1 / tz, -ly), ly) * tz;

    const float fx = (float)IMG_W / (2.0f * TANFOVX);
    const float fy = (float)IMG_H / (2.0f * TANFOVY);
    const float itz = 1.0f / tz;
    const float j00 = fx * itz;
    const float j02 = -fx * tx * itz * itz;
    const float j11 = fy * itz;
    const float j12 = -fy * ty * itz * itz;

    // Wr[j][k] = V[k][j];  Tm = J @ Wr  (2x3)
    float T0[3], T1[3];
    #pragma unroll
    for (int k = 0; k < 3; k++) {
        const float w0k = vm[k * 4 + 0]; // Wr[0][k]
        const float w1k = vm[k * 4 + 1]; // Wr[1][k]
        const float w2k = vm[k * 4 + 2]; // Wr[2][k]
        T0[k] = j00 * w0k + j02 * w2k;
        T1[k] = j11 * w1k + j12 * w2k;
    }

    // cov2d = Tm Sigma Tm^T
    float u[3], v[3];
    #pragma unroll
    for (int a = 0; a < 3; a++) {
        u[a] = S[a][0] * T0[0] + S[a][1] * T0[1] + S[a][2] * T0[2];
        v[a] = S[a][0] * T1[0] + S[a][1] * T1[1] + S[a][2] * T1[2];
    }
    const float cov00 = T0[0] * u[0] + T0[1] * u[1] + T0[2] * u[2];
    const float cov01 = T1[0] * u[0] + T1[1] * u[1] + T1[2] * u[2];
    const float cov11 = T1[0] * v[0] + T1[1] * v[1] + T1[2] * v[2];

    const float c00 = cov00 + 0.3f;
    const float c11 = cov11 + 0.3f;
    const float c01 = cov01;
    const float det = c00 * c11 - c01 * c01;
    const bool valid = in_frustum && (det > 0.0f);
    const float det_s = (det > 0.0f) ? det : 1.0f;
    const float idet = 1.0f / det_s;

    const float mid = 0.5f * (c00 + c11);
    const float lam1 = mid + sqrtf(fmaxf(0.1f, mid * mid - det));
    const int radii = valid ? (int)ceilf(3.0f * sqrtf(lam1)) : 0;
    out_radii[i] = (float)radii;  // radii kept in ORIGINAL order

    // stash params (original index)
    s_px[i] = ((pp0 + 1.0f) * (float)IMG_W - 1.0f) * 0.5f;
    s_py[i] = ((pp1 + 1.0f) * (float)IMG_H - 1.0f) * 0.5f;
    s_cA[i] = valid ? c11 * idet : 0.0f;
    s_cB[i] = valid ? -c01 * idet : 0.0f;
    s_cC[i] = valid ? c00 * idet : 0.0f;
    s_op[i] = valid ? opacities[i] : 0.0f;   // invalid => alpha==0 => skip
    s_cr[i] = colors[3 * i + 0];
    s_cg[i] = colors[3 * i + 1];
    s_cb[i] = colors[3 * i + 2];

    // ---- bitonic sort by depth (ascending), payload = index ----
    s_key[i] = depth;
    s_idx[i] = i;
    __syncthreads();
    for (int k = 2; k <= PMAX; k <<= 1) {
        for (int j = k >> 1; j > 0; j >>= 1) {
            const int ixj = i ^ j;
            if (ixj > i) {
                const bool up = ((i & k) == 0);
                const float a = s_key[i], b = s_key[ixj];
                if ((a > b) == up) {
                    s_key[i] = b; s_key[ixj] = a;
                    const int t = s_idx[i]; s_idx[i] = s_idx[ixj]; s_idx[ixj] = t;
                }
            }
            __syncthreads();
        }
    }

    // gather into depth order and publish
    const int src = s_idx[i];
    g_px[i] = s_px[src];
    g_py[i] = s_py[src];
    g_cA[i] = s_cA[src];
    g_cB[i] = s_cB[src];
    g_cC[i] = s_cC[src];
    g_op[i] = s_op[src];
    g_cr[i] = s_cr[src];
    g_cg[i] = s_cg[src];
    g_cb[i] = s_cb[src];
}

// ---------------------------------------------------------------------------
// Kernel 2: per-pixel front-to-back compositing with early termination.
// One thread per pixel; gaussian params broadcast from shared memory.
// ---------------------------------------------------------------------------
__global__ void __launch_bounds__(256) render_kernel(
    const float* __restrict__ bg,
    float* __restrict__ out_img)  // [3, H, W]
{
    __shared__ float hpx[PMAX], hpy[PMAX];
    __shared__ float hA[PMAX], hB[PMAX], hC[PMAX];
    __shared__ float hop[PMAX];
    __shared__ float hr[PMAX], hg[PMAX], hb[PMAX];

    const int t = threadIdx.x;
    hpx[t] = g_px[t]; hpy[t] = g_py[t];
    hA[t] = g_cA[t];  hB[t] = g_cB[t]; hC[t] = g_cC[t];
    hop[t] = g_op[t];
    hr[t] = g_cr[t];  hg[t] = g_cg[t]; hb[t] = g_cb[t];
    __syncthreads();

    const int pix = blockIdx.x * blockDim.x + t;
    if (pix >= NPIX) return;
    const float xf = (float)(pix % IMG_W);
    const float yf = (float)(pix / IMG_W);

    float T = 1.0f;
    float cr = 0.0f, cg = 0.0f, cb = 0.0f;

    for (int i = 0; i < PMAX; i++) {
        const float dx = hpx[i] - xf;
        const float dy = hpy[i] - yf;
        const float power = -0.5f * (hA[i] * dx * dx + hC[i] * dy * dy) - hB[i] * dx * dy;
        float alpha = 0.0f;
        if (power <= 0.0f) {
            float a = hop[i] * expf(power);
            a = fminf(0.99f, a);
            if (a >= ALPHA_MIN) alpha = a;
        }
        const float test = T * (1.0f - alpha);
        if (test < T_EPS) break;  // stop: this and all later gaussians contribute 0
        const float w = alpha * T;
        cr += w * hr[i];
        cg += w * hg[i];
        cb += w * hb[i];
        T = test;
    }

    out_img[0 * NPIX + pix] = cr + bg[0] * T;
    out_img[1 * NPIX + pix] = cg + bg[1] * T;
    out_img[2 * NPIX + pix] = cb + bg[2] * T;
}

extern "C" void kernel_launch(void* const* d_in, const int* in_sizes, int n_in,
                              void* d_out, int out_size) {
    const float* means3D   = (const float*)d_in[0];
    // d_in[1] = means2D (unused)
    const float* opacities = (const float*)d_in[2];
    const float* colors    = (const float*)d_in[3];
    const float* scales    = (const float*)d_in[4];
    const float* rotations = (const float*)d_in[5];
    const float* bg        = (const float*)d_in[6];
    const float* viewm     = (const float*)d_in[7];
    const float* projm     = (const float*)d_in[8];

    float* out = (float*)d_out;
    float* out_radii = out + 3 * NPIX;  // radii tail (as float values)

    preprocess_kernel<<<1, PMAX>>>(means3D, opacities, colors, scales,
                                   rotations, viewm, projm, out_radii);
    render_kernel<<<(NPIX + 255) / 256, 256>>>(bg, out);
}

// round 2
// speedup vs baseline: 2.4127x; 2.4127x over previous
#include <cuda_runtime.h>
#include <math.h>

#define IMG_H 192
#define IMG_W 192
#define NPIX (IMG_H * IMG_W)
#define PMAX 256
#define TILE 16
#define TILES_X (IMG_W / TILE)
#define NTILES ((IMG_H / TILE) * (IMG_W / TILE))
#define TANFOVX 0.5f
#define TANFOVY 0.5f
#define NEAR_P 0.2f
#define ALPHA_MIN (1.0f / 255.0f)
#define T_EPS 1e-4f

// Depth-sorted gaussian params, packed for the render kernel.
// q1 = (px, py, -0.5*conA, -conB)   q2 = (-0.5*conC, op, col_r, col_g)
__device__ float4 g_q1[PMAX];
__device__ float4 g_q2[PMAX];
__device__ float  g_cbv[PMAX];   // col_b
__device__ float  g_r2[PMAX];    // conservative cutoff radius^2 (alpha<1/255 outside)

// ---------------------------------------------------------------------------
// Kernel 1: preprocess + bitonic depth sort (one block, 256 threads).
// ---------------------------------------------------------------------------
__global__ void preprocess_kernel(
    const float* __restrict__ means3D,
    const float* __restrict__ opacities,
    const float* __restrict__ colors,
    const float* __restrict__ scales,
    const float* __restrict__ rotations,
    const float* __restrict__ viewmatrix,
    const float* __restrict__ projmatrix,
    float* __restrict__ out_radii)
{
    const int i = threadIdx.x;

    __shared__ float s_key[PMAX];
    __shared__ int   s_idx[PMAX];
    __shared__ float s_px[PMAX], s_py[PMAX];
    __shared__ float s_cA[PMAX], s_cB[PMAX], s_cC[PMAX];
    __shared__ float s_op[PMAX];
    __shared__ float s_cr[PMAX], s_cg[PMAX], s_cb[PMAX];
    __shared__ float s_r2[PMAX];

    const float mx = means3D[3 * i + 0];
    const float my = means3D[3 * i + 1];
    const float mz = means3D[3 * i + 2];
    const float* vm = viewmatrix;
    const float* pm = projmatrix;

    const float pv0 = mx * vm[0] + my * vm[4] + mz * vm[8]  + vm[12];
    const float pv1 = mx * vm[1] + my * vm[5] + mz * vm[9]  + vm[13];
    const float pv2 = mx * vm[2] + my * vm[6] + mz * vm[10] + vm[14];

    const float ph0 = mx * pm[0] + my * pm[4] + mz * pm[8]  + pm[12];
    const float ph1 = mx * pm[1] + my * pm[5] + mz * pm[9]  + pm[13];
    const float ph3 = mx * pm[3] + my * pm[7] + mz * pm[11] + pm[15];
    const float inv_w = 1.0f / (ph3 + 1e-7f);
    const float pp0 = ph0 * inv_w;
    const float pp1 = ph1 * inv_w;

    const float depth = pv2;
    const bool in_frustum = depth > NEAR_P;

    float qr = rotations[4 * i + 0];
    float qx = rotations[4 * i + 1];
    float qy = rotations[4 * i + 2];
    float qz = rotations[4 * i + 3];
    {
        const float qn = rsqrtf(qr * qr + qx * qx + qy * qy + qz * qz);
        qr *= qn; qx *= qn; qy *= qn; qz *= qn;
    }
    float R[3][3];
    R[0][0] = 1.f - 2.f * (qy * qy + qz * qz);
    R[0][1] = 2.f * (qx * qy - qr * qz);
    R[0][2] = 2.f * (qx * qz + qr * qy);
    R[1][0] = 2.f * (qx * qy + qr * qz);
    R[1][1] = 1.f - 2.f * (qx * qx + qz * qz);
    R[1][2] = 2.f * (qy * qz - qr * qx);
    R[2][0] = 2.f * (qx * qz - qr * qy);
    R[2][1] = 2.f * (qy * qz + qr * qx);
    R[2][2] = 1.f - 2.f * (qx * qx + qy * qy);

    const float s0 = scales[3 * i + 0];
    const float s1 = scales[3 * i + 1];
    const float s2v = scales[3 * i + 2];
    const float w0 = s0 * s0, w1 = s1 * s1, w2 = s2v * s2v;

    float S[3][3];
    #pragma unroll
    for (int a = 0; a < 3; a++)
        #pragma unroll
        for (int b = 0; b < 3; b++)
            S[a][b] = R[a][0] * w0 * R[b][0] + R[a][1] * w1 * R[b][1] + R[a][2] * w2 * R[b][2];

    const float tz = in_frustum ? depth : 1.0f;
    const float lx = 1.3f * TANFOVX, ly = 1.3f * TANFOVY;
    const float tx = fminf(fmaxf(pv0 / tz, -lx), lx) * tz;
    const float ty = fminf(fmaxf(pv1 / tz, -ly), ly) * tz;

    const float fx = (float)IMG_W / (2.0f * TANFOVX);
    const float fy = (float)IMG_H / (2.0f * TANFOVY);
    const float itz = 1.0f / tz;
    const float j00 = fx * itz;
    const float j02 = -fx * tx * itz * itz;
    const float j11 = fy * itz;
    const float j12 = -fy * ty * itz * itz;

    float T0[3], T1[3];
    #pragma unroll
    for (int k = 0; k < 3; k++) {
        const float w0k = vm[k * 4 + 0];
        const float w1k = vm[k * 4 + 1];
        const float w2k = vm[k * 4 + 2];
        T0[k] = j00 * w0k + j02 * w2k;
        T1[k] = j11 * w1k + j12 * w2k;
    }

    float u[3], v[3];
    #pragma unroll
    for (int a = 0; a < 3; a++) {
        u[a] = S[a][0] * T0[0] + S[a][1] * T0[1] + S[a][2] * T0[2];
        v[a] = S[a][0] * T1[0] + S[a][1] * T1[1] + S[a][2] * T1[2];
    }
    const float cov00 = T0[0] * u[0] + T0[1] * u[1] + T0[2] * u[2];
    const float cov01 = T1[0] * u[0] + T1[1] * u[1] + T1[2] * u[2];
    const float cov11 = T1[0] * v[0] + T1[1] * v[1] + T1[2] * v[2];

    const float c00 = cov00 + 0.3f;
    const float c11 = cov11 + 0.3f;
    const float c01 = cov01;
    const float det = c00 * c11 - c01 * c01;
    const bool valid = in_frustum && (det > 0.0f);
    const float det_s = (det > 0.0f) ? det : 1.0f;
    const float idet = 1.0f / det_s;

    const float mid = 0.5f * (c00 + c11);
    const float lam1 = mid + sqrtf(fmaxf(0.1f, mid * mid - det));
    const int radii = valid ? (int)ceilf(3.0f * sqrtf(lam1)) : 0;
    out_radii[i] = (float)radii;

    const float op = opacities[i];

    s_px[i] = ((pp0 + 1.0f) * (float)IMG_W - 1.0f) * 0.5f;
    s_py[i] = ((pp1 + 1.0f) * (float)IMG_H - 1.0f) * 0.5f;
    s_cA[i] = valid ? c11 * idet : 0.0f;
    s_cB[i] = valid ? -c01 * idet : 0.0f;
    s_cC[i] = valid ? c00 * idet : 0.0f;
    s_op[i] = valid ? op : 0.0f;
    s_cr[i] = colors[3 * i + 0];
    s_cg[i] = colors[3 * i + 1];
    s_cb[i] = colors[3 * i + 2];

    // Conservative cull radius: outside r, alpha < 1/255 guaranteed
    // (power <= -0.5*d^2/lam1(cov);  op*exp(power) < AMIN  <=>  d^2 > 2*lam1*ln(255*op))
    float r2 = -1.0f;
    if (valid && op > ALPHA_MIN) {
        r2 = 2.0f * lam1 * logf(255.0f * op) * 1.0001f + 1e-3f;  // safety margin
    }
    s_r2[i] = r2;

    // bitonic sort by depth ascending
    s_key[i] = depth;
    s_idx[i] = i;
    __syncthreads();
    for (int k = 2; k <= PMAX; k <<= 1) {
        for (int j = k >> 1; j > 0; j >>= 1) {
            const int ixj = i ^ j;
            if (ixj > i) {
                const bool up = ((i & k) == 0);
                const float a = s_key[i], b = s_key[ixj];
                if ((a > b) == up) {
                    s_key[i] = b; s_key[ixj] = a;
                    const int tmp = s_idx[i]; s_idx[i] = s_idx[ixj]; s_idx[ixj] = tmp;
                }
            }
            __syncthreads();
        }
    }

    const int src = s_idx[i];
    g_q1[i]  = make_float4(s_px[src], s_py[src], -0.5f * s_cA[src], -s_cB[src]);
    g_q2[i]  = make_float4(-0.5f * s_cC[src], s_op[src], s_cr[src], s_cg[src]);
    g_cbv[i] = s_cb[src];
    g_r2[i]  = s_r2[src];
}

// ---------------------------------------------------------------------------
// Kernel 2: one block per 16x16 tile. Cull gaussians to the tile (ordered
// compaction), then per-pixel front-to-back compositing.
// ---------------------------------------------------------------------------
__global__ void __launch_bounds__(256) render_kernel(
    const float* __restrict__ bg,
    float* __restrict__ out_img)
{
    __shared__ float4 sq1[PMAX];
    __shared__ float4 sq2[PMAX];
    __shared__ float  scb[PMAX];
    __shared__ int warp_cnt[8];
    __shared__ int warp_off[8];
    __shared__ int s_count;

    const int t = threadIdx.x;
    const int tile = blockIdx.x;
    const int tx0 = (tile % TILES_X) * TILE;
    const int ty0 = (tile / TILES_X) * TILE;
    const float tx0f = (float)tx0, tx1f = (float)(tx0 + TILE - 1);
    const float ty0f = (float)ty0, ty1f = (float)(ty0 + TILE - 1);

    // per-thread gaussian t: tile intersection test
    const float4 q1 = g_q1[t];
    const float4 q2 = g_q2[t];
    const float cbv = g_cbv[t];
    const float r2  = g_r2[t];

    const float ndx = fminf(fmaxf(q1.x, tx0f), tx1f) - q1.x;
    const float ndy = fminf(fmaxf(q1.y, ty0f), ty1f) - q1.y;
    const bool inc = (ndx * ndx + ndy * ndy) <= r2;

    // ordered compaction (preserves depth order)
    const unsigned bmask = __ballot_sync(0xffffffffu, inc);
    const int lane = t & 31, wid = t >> 5;
    if (lane == 0) warp_cnt[wid] = __popc(bmask);
    __syncthreads();
    if (t == 0) {
        int acc = 0;
        #pragma unroll
        for (int w = 0; w < 8; w++) { warp_off[w] = acc; acc += warp_cnt[w]; }
        s_count = acc;
    }
    __syncthreads();
    if (inc) {
        const int pos = warp_off[wid] + __popc(bmask & ((1u << lane) - 1u));
        sq1[pos] = q1;
        sq2[pos] = q2;
        scb[pos] = cbv;
    }
    __syncthreads();

    const int N = s_count;
    const int lx = t & (TILE - 1);
    const int ly = t >> 4;
    const float xf = (float)(tx0 + lx);
    const float yf = (float)(ty0 + ly);

    float T = 1.0f;
    float cr = 0.0f, cg = 0.0f, cb = 0.0f;

    #pragma unroll 4
    for (int j = 0; j < N; j++) {
        const float4 a1 = sq1[j];
        const float4 a2 = sq2[j];
        const float dx = a1.x - xf;
        const float dy = a1.y - yf;
        const float power = fmaf(a1.z, dx * dx, fmaf(a2.x, dy * dy, a1.w * (dx * dy)));
        const float g = __expf(fminf(power, 0.0f));
        const float a = fminf(0.99f, a2.y * g);
        const float alpha = (power > 0.0f || a < ALPHA_MIN) ? 0.0f : a;
        const float test = T * (1.0f - alpha);
        if (test < T_EPS) break;
        const float w = alpha * T;
        cr = fmaf(w, a2.z, cr);
        cg = fmaf(w, a2.w, cg);
        cb = fmaf(w, scb[j], cb);
        T = test;
    }

    const int pix = (ty0 + ly) * IMG_W + tx0 + lx;
    out_img[0 * NPIX + pix] = cr + bg[0] * T;
    out_img[1 * NPIX + pix] = cg + bg[1] * T;
    out_img[2 * NPIX + pix] = cb + bg[2] * T;
}

extern "C" void kernel_launch(void* const* d_in, const int* in_sizes, int n_in,
                              void* d_out, int out_size) {
    const float* means3D   = (const float*)d_in[0];
    const float* opacities = (const float*)d_in[2];
    const float* colors    = (const float*)d_in[3];
    const float* scales    = (const float*)d_in[4];
    const float* rotations = (const float*)d_in[5];
    const float* bg        = (const float*)d_in[6];
    const float* viewm     = (const float*)d_in[7];
    const float* projm     = (const float*)d_in[8];

    float* out = (float*)d_out;
    float* out_radii = out + 3 * NPIX;

    preprocess_kernel<<<1, PMAX>>>(means3D, opacities, colors, scales,
                                   rotations, viewm, projm, out_radii);
    render_kernel<<<NTILES, 256>>>(bg, out);
}

// round 7
// speedup vs baseline: 2.7694x; 1.1479x over previous
#include <cuda_runtime.h>
#include <math.h>

#define IMG_H 192
#define IMG_W 192
#define NPIX (IMG_H * IMG_W)
#define PMAX 256
#define TILE 16
#define TILES_X (IMG_W / TILE)
#define NTILES ((IMG_H / TILE) * (IMG_W / TILE))
#define TANFOVX 0.5f
#define TANFOVY 0.5f
#define NEAR_P 0.2f
#define ALPHA_MIN (1.0f / 255.0f)
#define T_EPS 1e-4f
#define KEY_INF __int_as_float(0x7f800000)

// ---------------------------------------------------------------------------
// Single fused kernel: one block per 16x16 tile (144 blocks = 1 wave).
// Each block independently preprocesses all 256 gaussians (thread i ->
// gaussian i), culls to its tile, rank-orders the survivors by (depth, index)
// in ONE shared-memory pass, then composites its 256 pixels front-to-back.
// ---------------------------------------------------------------------------
__global__ void __launch_bounds__(256) fused_kernel(
    const float* __restrict__ means3D,
    const float* __restrict__ opacities,
    const float* __restrict__ colors,
    const float* __restrict__ scales,
    const float* __restrict__ rotations,
    const float* __restrict__ viewmatrix,
    const float* __restrict__ projmatrix,
    const float* __restrict__ bg,
    float* __restrict__ out_img,     // [3, H, W]
    float* __restrict__ out_radii)   // [P] (radii as float values)
{
    __shared__ __align__(16) float s_key[PMAX];   // inc ? depth : +INF
    // tile-compacted, depth-ordered params
    __shared__ float4 cq1[PMAX];     // (px, py, -0.5*conA, -conB)
    __shared__ float4 cq2[PMAX];     // (-0.5*conC, op, col_r, col_g)
    __shared__ float  ccb[PMAX];     // col_b

    const int i = threadIdx.x;
    const int tile = blockIdx.x;
    const int tx0 = (tile % TILES_X) * TILE;
    const int ty0 = (tile / TILES_X) * TILE;

    // ================= per-gaussian preprocessing (thread i = gaussian i) ===
    const float mx = means3D[3 * i + 0];
    const float my = means3D[3 * i + 1];
    const float mz = means3D[3 * i + 2];
    const float colr = colors[3 * i + 0];
    const float colg = colors[3 * i + 1];
    const float colb = colors[3 * i + 2];
    const float op   = opacities[i];
    // hoist bg loads: overlap their latency with all the math below
    const float bg0 = bg[0], bg1 = bg[1], bg2 = bg[2];
    const float* vm = viewmatrix;
    const float* pm = projmatrix;

    const float pv0 = mx * vm[0] + my * vm[4] + mz * vm[8]  + vm[12];
    const float pv1 = mx * vm[1] + my * vm[5] + mz * vm[9]  + vm[13];
    const float pv2 = mx * vm[2] + my * vm[6] + mz * vm[10] + vm[14];

    const float ph0 = mx * pm[0] + my * pm[4] + mz * pm[8]  + pm[12];
    const float ph1 = mx * pm[1] + my * pm[5] + mz * pm[9]  + pm[13];
    const float ph3 = mx * pm[3] + my * pm[7] + mz * pm[11] + pm[15];
    const float inv_w = 1.0f / (ph3 + 1e-7f);
    const float pp0 = ph0 * inv_w;
    const float pp1 = ph1 * inv_w;

    const float depth = pv2;
    const bool in_frustum = depth > NEAR_P;

    float qr = rotations[4 * i + 0];
    float qx = rotations[4 * i + 1];
    float qy = rotations[4 * i + 2];
    float qz = rotations[4 * i + 3];
    {
        const float qn = rsqrtf(qr * qr + qx * qx + qy * qy + qz * qz);
        qr *= qn; qx *= qn; qy *= qn; qz *= qn;
    }
    float R[3][3];
    R[0][0] = 1.f - 2.f * (qy * qy + qz * qz);
    R[0][1] = 2.f * (qx * qy - qr * qz);
    R[0][2] = 2.f * (qx * qz + qr * qy);
    R[1][0] = 2.f * (qx * qy + qr * qz);
    R[1][1] = 1.f - 2.f * (qx * qx + qz * qz);
    R[1][2] = 2.f * (qy * qz - qr * qx);
    R[2][0] = 2.f * (qx * qz - qr * qy);
    R[2][1] = 2.f * (qy * qz + qr * qx);
    R[2][2] = 1.f - 2.f * (qx * qx + qy * qy);

    const float s0 = scales[3 * i + 0];
    const float s1 = scales[3 * i + 1];
    const float s2v = scales[3 * i + 2];
    const float w0 = s0 * s0, w1 = s1 * s1, w2 = s2v * s2v;

    float S[3][3];
    #pragma unroll
    for (int a = 0; a < 3; a++)
        #pragma unroll
        for (int b = 0; b < 3; b++)
            S[a][b] = R[a][0] * w0 * R[b][0] + R[a][1] * w1 * R[b][1] + R[a][2] * w2 * R[b][2];

    const float tz = in_frustum ? depth : 1.0f;
    const float lxc = 1.3f * TANFOVX, lyc = 1.3f * TANFOVY;
    const float txv = fminf(fmaxf(pv0 / tz, -lxc), lxc) * tz;
    const float tyv = fminf(fmaxf(pv1 / tz, -lyc), lyc) * tz;

    const float fx = (float)IMG_W / (2.0f * TANFOVX);
    const float fy = (float)IMG_H / (2.0f * TANFOVY);
    const float itz = 1.0f / tz;
    const float j00 = fx * itz;
    const float j02 = -fx * txv * itz * itz;
    const float j11 = fy * itz;
    const float j12 = -fy * tyv * itz * itz;

    float T0[3], T1[3];
    #pragma unroll
    for (int k = 0; k < 3; k++) {
        const float w0k = vm[k * 4 + 0];
        const float w1k = vm[k * 4 + 1];
        const float w2k = vm[k * 4 + 2];
        T0[k] = j00 * w0k + j02 * w2k;
        T1[k] = j11 * w1k + j12 * w2k;
    }

    float u[3], v[3];
    #pragma unroll
    for (int a = 0; a < 3; a++) {
        u[a] = S[a][0] * T0[0] + S[a][1] * T0[1] + S[a][2] * T0[2];
        v[a] = S[a][0] * T1[0] + S[a][1] * T1[1] + S[a][2] * T1[2];
    }
    const float cov00 = T0[0] * u[0] + T0[1] * u[1] + T0[2] * u[2];
    const float cov01 = T1[0] * u[0] + T1[1] * u[1] + T1[2] * u[2];
    const float cov11 = T1[0] * v[0] + T1[1] * v[1] + T1[2] * v[2];

    const float c00 = cov00 + 0.3f;
    const float c11 = cov11 + 0.3f;
    const float c01 = cov01;
    const float det = c00 * c11 - c01 * c01;
    const bool valid = in_frustum && (det > 0.0f);
    const float det_s = (det > 0.0f) ? det : 1.0f;
    const float idet = 1.0f / det_s;

    const float mid = 0.5f * (c00 + c11);
    const float lam1 = mid + sqrtf(fmaxf(0.1f, mid * mid - det));
    if (tile == 0) {
        const int radii = valid ? (int)ceilf(3.0f * sqrtf(lam1)) : 0;
        out_radii[i] = (float)radii;
    }

    const float pxs = ((pp0 + 1.0f) * (float)IMG_W - 1.0f) * 0.5f;
    const float pys = ((pp1 + 1.0f) * (float)IMG_H - 1.0f) * 0.5f;
    const float cA = valid ? c11 * idet : 0.0f;
    const float cB = valid ? -c01 * idet : 0.0f;
    const float cC = valid ? c00 * idet : 0.0f;
    const float ops = valid ? op : 0.0f;

    // Conservative cull radius: outside it, alpha < 1/255 guaranteed
    // (power <= -0.5*d^2/lam1;  op*exp(power) < AMIN  <=>  d^2 > 2*lam1*ln(255*op))
    float r2 = -1.0f;
    if (valid && op > ALPHA_MIN) {
        r2 = 2.0f * lam1 * logf(255.0f * op) * 1.0001f + 1e-3f;
    }

    // ================= tile cull ===========================================
    const float tx0f = (float)tx0, tx1f = (float)(tx0 + TILE - 1);
    const float ty0f = (float)ty0, ty1f = (float)(ty0 + TILE - 1);
    const float ndx = fminf(fmaxf(pxs, tx0f), tx1f) - pxs;
    const float ndy = fminf(fmaxf(pys, ty0f), ty1f) - pys;
    const bool inc = (ndx * ndx + ndy * ndy) <= r2;

    // ================= fused rank (stable by depth, then index) + count =====
    s_key[i] = inc ? depth : KEY_INF;
    __syncthreads();

    const float ki = inc ? depth : KEY_INF;
    int pos = 0;
    int N = 0;
    const float4* key4 = (const float4*)s_key;
    #pragma unroll 4
    for (int j4 = 0; j4 < PMAX / 4; j4++) {
        const float4 kv = key4[j4];
        const int j = j4 * 4;
        N   += (kv.x < KEY_INF) + (kv.y < KEY_INF) + (kv.z < KEY_INF) + (kv.w < KEY_INF);
        pos += (kv.x < ki) || (kv.x == ki && (j + 0) < i);
        pos += (kv.y < ki) || (kv.y == ki && (j + 1) < i);
        pos += (kv.z < ki) || (kv.z == ki && (j + 2) < i);
        pos += (kv.w < ki) || (kv.w == ki && (j + 3) < i);
    }

    if (inc) {
        cq1[pos] = make_float4(pxs, pys, -0.5f * cA, -cB);
        cq2[pos] = make_float4(-0.5f * cC, ops, colr, colg);
        ccb[pos] = colb;
    }
    __syncthreads();

    // ================= per-pixel compositing ================================
    const int lx = i & (TILE - 1);
    const int ly = i >> 4;
    const float xf = (float)(tx0 + lx);
    const float yf = (float)(ty0 + ly);

    float T = 1.0f;
    float cr = 0.0f, cg = 0.0f, cb = 0.0f;

    #pragma unroll 4
    for (int j = 0; j < N; j++) {
        const float4 a1 = cq1[j];
        const float4 a2 = cq2[j];
        const float dx = a1.x - xf;
        const float dy = a1.y - yf;
        const float power = fmaf(a1.z, dx * dx, fmaf(a2.x, dy * dy, a1.w * (dx * dy)));
        const float g = __expf(fminf(power, 0.0f));
        const float a = fminf(0.99f, a2.y * g);
        const float alpha = (power > 0.0f || a < ALPHA_MIN) ? 0.0f : a;
        const float test = T * (1.0f - alpha);
        if (test < T_EPS) break;
        const float w = alpha * T;
        cr = fmaf(w, a2.z, cr);
        cg = fmaf(w, a2.w, cg);
        cb = fmaf(w, ccb[j], cb);
        T = test;
    }

    const int pix = (ty0 + ly) * IMG_W + tx0 + lx;
    out_img[0 * NPIX + pix] = cr + bg0 * T;
    out_img[1 * NPIX + pix] = cg + bg1 * T;
    out_img[2 * NPIX + pix] = cb + bg2 * T;
}

extern "C" void kernel_launch(void* const* d_in, const int* in_sizes, int n_in,
                              void* d_out, int out_size) {
    const float* means3D   = (const float*)d_in[0];
    const float* opacities = (const float*)d_in[2];
    const float* colors    = (const float*)d_in[3];
    const float* scales    = (const float*)d_in[4];
    const float* rotations = (const float*)d_in[5];
    const float* bg        = (const float*)d_in[6];
    const float* viewm     = (const float*)d_in[7];
    const float* projm     = (const float*)d_in[8];

    float* out = (float*)d_out;
    float* out_radii = out + 3 * NPIX;

    fused_kernel<<<NTILES, 256>>>(means3D, opacities, colors, scales,
                                  rotations, viewm, projm, bg, out, out_radii);
}

// round 11
// speedup vs baseline: 3.2985x; 1.1910x over previous
#include <cuda_runtime.h>
#include <math.h>

#define IMG_H 192
#define IMG_W 192
#define NPIX (IMG_H * IMG_W)
#define PMAX 256
#define TILE 16
#define TILES_X (IMG_W / TILE)
#define NTILES ((IMG_H / TILE) * (IMG_W / TILE))
#define TANFOVX 0.5f
#define TANFOVY 0.5f
#define NEAR_P 0.2f
#define ALPHA_MIN (1.0f / 255.0f)
#define T_EPS 1e-4f

// ---------------------------------------------------------------------------
// Single fused kernel: one block per 16x16 tile (144 blocks = 1 wave).
// Each block preprocesses all 256 gaussians (thread i -> gaussian i), culls to
// its tile (ellipse-bbox AND bounding-circle, both conservative), rank-orders
// survivors by (depth, index) via u64 keys, then composites its 256 pixels.
// ---------------------------------------------------------------------------
__global__ void __launch_bounds__(256) fused_kernel(
    const float* __restrict__ means3D,
    const float* __restrict__ opacities,
    const float* __restrict__ colors,
    const float* __restrict__ scales,
    const float* __restrict__ rotations,
    const float* __restrict__ viewmatrix,
    const float* __restrict__ projmatrix,
    const float* __restrict__ bg,
    float* __restrict__ out_img,     // [3, H, W]
    float* __restrict__ out_radii)   // [P] (radii as float values)
{
    __shared__ __align__(16) unsigned long long s_key[PMAX]; // (depth_bits<<32)|idx, or MAX
    // tile-compacted, depth-ordered params
    __shared__ float4 cq1[PMAX];     // (px, py, -0.5*conA, -conB)
    __shared__ float4 cq2[PMAX];     // (-0.5*conC, op, col_r, col_g)
    __shared__ float  ccb[PMAX];     // col_b

    const int i = threadIdx.x;
    const int tile = blockIdx.x;
    const int tx0 = (tile % TILES_X) * TILE;
    const int ty0 = (tile / TILES_X) * TILE;

    // ================= per-gaussian preprocessing (thread i = gaussian i) ===
    const float mx = means3D[3 * i + 0];
    const float my = means3D[3 * i + 1];
    const float mz = means3D[3 * i + 2];
    const float colr = colors[3 * i + 0];
    const float colg = colors[3 * i + 1];
    const float colb = colors[3 * i + 2];
    const float op   = opacities[i];
    const float bg0 = bg[0], bg1 = bg[1], bg2 = bg[2];
    const float* vm = viewmatrix;
    const float* pm = projmatrix;

    const float pv0 = mx * vm[0] + my * vm[4] + mz * vm[8]  + vm[12];
    const float pv1 = mx * vm[1] + my * vm[5] + mz * vm[9]  + vm[13];
    const float pv2 = mx * vm[2] + my * vm[6] + mz * vm[10] + vm[14];

    const float ph0 = mx * pm[0] + my * pm[4] + mz * pm[8]  + pm[12];
    const float ph1 = mx * pm[1] + my * pm[5] + mz * pm[9]  + pm[13];
    const float ph3 = mx * pm[3] + my * pm[7] + mz * pm[11] + pm[15];
    const float inv_w = 1.0f / (ph3 + 1e-7f);
    const float pp0 = ph0 * inv_w;
    const float pp1 = ph1 * inv_w;

    const float depth = pv2;
    const bool in_frustum = depth > NEAR_P;

    float qr = rotations[4 * i + 0];
    float qx = rotations[4 * i + 1];
    float qy = rotations[4 * i + 2];
    float qz = rotations[4 * i + 3];
    {
        const float qn = rsqrtf(qr * qr + qx * qx + qy * qy + qz * qz);
        qr *= qn; qx *= qn; qy *= qn; qz *= qn;
    }
    float R[3][3];
    R[0][0] = 1.f - 2.f * (qy * qy + qz * qz);
    R[0][1] = 2.f * (qx * qy - qr * qz);
    R[0][2] = 2.f * (qx * qz + qr * qy);
    R[1][0] = 2.f * (qx * qy + qr * qz);
    R[1][1] = 1.f - 2.f * (qx * qx + qz * qz);
    R[1][2] = 2.f * (qy * qz - qr * qx);
    R[2][0] = 2.f * (qx * qz - qr * qy);
    R[2][1] = 2.f * (qy * qz + qr * qx);
    R[2][2] = 1.f - 2.f * (qx * qx + qy * qy);

    const float s0 = scales[3 * i + 0];
    const float s1 = scales[3 * i + 1];
    const float s2v = scales[3 * i + 2];
    const float w0 = s0 * s0, w1 = s1 * s1, w2 = s2v * s2v;

    float S[3][3];
    #pragma unroll
    for (int a = 0; a < 3; a++)
        #pragma unroll
        for (int b = 0; b < 3; b++)
            S[a][b] = R[a][0] * w0 * R[b][0] + R[a][1] * w1 * R[b][1] + R[a][2] * w2 * R[b][2];

    const float tz = in_frustum ? depth : 1.0f;
    const float lxc = 1.3f * TANFOVX, lyc = 1.3f * TANFOVY;
    const float txv = fminf(fmaxf(pv0 / tz, -lxc), lxc) * tz;
    const float tyv = fminf(fmaxf(pv1 / tz, -lyc), lyc) * tz;

    const float fx = (float)IMG_W / (2.0f * TANFOVX);
    const float fy = (float)IMG_H / (2.0f * TANFOVY);
    const float itz = 1.0f / tz;
    const float j00 = fx * itz;
    const float j02 = -fx * txv * itz * itz;
    const float j11 = fy * itz;
    const float j12 = -fy * tyv * itz * itz;

    float T0[3], T1[3];
    #pragma unroll
    for (int k = 0; k < 3; k++) {
        const float w0k = vm[k * 4 + 0];
        const float w1k = vm[k * 4 + 1];
        const float w2k = vm[k * 4 + 2];
        T0[k] = j00 * w0k + j02 * w2k;
        T1[k] = j11 * w1k + j12 * w2k;
    }

    float u[3], v[3];
    #pragma unroll
    for (int a = 0; a < 3; a++) {
        u[a] = S[a][0] * T0[0] + S[a][1] * T0[1] + S[a][2] * T0[2];
        v[a] = S[a][0] * T1[0] + S[a][1] * T1[1] + S[a][2] * T1[2];
    }
    const float cov00 = T0[0] * u[0] + T0[1] * u[1] + T0[2] * u[2];
    const float cov01 = T1[0] * u[0] + T1[1] * u[1] + T1[2] * u[2];
    const float cov11 = T1[0] * v[0] + T1[1] * v[1] + T1[2] * v[2];

    const float c00 = cov00 + 0.3f;
    const float c11 = cov11 + 0.3f;
    const float c01 = cov01;
    const float det = c00 * c11 - c01 * c01;
    const bool valid = in_frustum && (det > 0.0f);
    const float det_s = (det > 0.0f) ? det : 1.0f;
    const float idet = 1.0f / det_s;

    const float mid = 0.5f * (c00 + c11);
    const float lam1 = mid + sqrtf(fmaxf(0.1f, mid * mid - det));
    if (tile == 0) {
        const int radii = valid ? (int)ceilf(3.0f * sqrtf(lam1)) : 0;
        out_radii[i] = (float)radii;
    }

    const float pxs = ((pp0 + 1.0f) * (float)IMG_W - 1.0f) * 0.5f;
    const float pys = ((pp1 + 1.0f) * (float)IMG_H - 1.0f) * 0.5f;
    const float cA = valid ? c11 * idet : 0.0f;
    const float cB = valid ? -c01 * idet : 0.0f;
    const float cC = valid ? c00 * idet : 0.0f;
    const float ops = valid ? op : 0.0f;

    // Conservative cull region: alpha >= 1/255 requires 0.5*d^T Con d <= L,
    // L = ln(255*op). Necessary conditions used (both conservative):
    //   circle:  |d|^2 <= 2*L*lam1
    //   bbox:    dx^2 <= 2*L*c00,  dy^2 <= 2*L*c11   (ellipse axis extents)
    float r2  = -1.0f;
    float wx2 = -1.0f;
    float wy2 = -1.0f;
    if (valid && op > ALPHA_MIN) {
        const float L2 = 2.0f * logf(255.0f * op) * 1.0001f;  // 2L + margin
        r2  = L2 * lam1 + 1e-3f;
        wx2 = L2 * c00  + 1e-3f;
        wy2 = L2 * c11  + 1e-3f;
    }

    // ================= tile cull ===========================================
    const float tx0f = (float)tx0, tx1f = (float)(tx0 + TILE - 1);
    const float ty0f = (float)ty0, ty1f = (float)(ty0 + TILE - 1);
    const float ndx = fminf(fmaxf(pxs, tx0f), tx1f) - pxs;
    const float ndy = fminf(fmaxf(pys, ty0f), ty1f) - pys;
    const float dx2 = ndx * ndx, dy2 = ndy * ndy;
    const bool inc = (dx2 <= wx2) && (dy2 <= wy2) && (dx2 + dy2 <= r2);

    // ================= stable rank via u64 keys + popc barrier ==============
    // key = (float_bits(depth) << 32) | index; depth > 0.2 for all included,
    // so positive-float bit pattern is order-isomorphic to float order.
    const unsigned long long ki = inc
        ? (((unsigned long long)__float_as_uint(depth) << 32) | (unsigned)i)
        : 0xFFFFFFFFFFFFFFFFull;
    s_key[i] = ki;
    const int N = __syncthreads_count(inc);   // barrier + survivor count

    int pos = 0;
    const ulonglong2* k2 = (const ulonglong2*)s_key;
    #pragma unroll 8
    for (int j2 = 0; j2 < PMAX / 2; j2++) {
        const ulonglong2 kv = k2[j2];
        pos += (kv.x < ki);
        pos += (kv.y < ki);
    }

    if (inc) {
        cq1[pos] = make_float4(pxs, pys, -0.5f * cA, -cB);
        cq2[pos] = make_float4(-0.5f * cC, ops, colr, colg);
        ccb[pos] = colb;
    }
    __syncthreads();

    // ================= per-pixel compositing ================================
    const int lx = i & (TILE - 1);
    const int ly = i >> 4;
    const float xf = (float)(tx0 + lx);
    const float yf = (float)(ty0 + ly);

    float T = 1.0f;
    float cr = 0.0f, cg = 0.0f, cb = 0.0f;

    #pragma unroll 4
    for (int j = 0; j < N; j++) {
        const float4 a1 = cq1[j];
        const float4 a2 = cq2[j];
        const float dx = a1.x - xf;
        const float dy = a1.y - yf;
        const float power = fmaf(a1.z, dx * dx, fmaf(a2.x, dy * dy, a1.w * (dx * dy)));
        const float g = __expf(fminf(power, 0.0f));
        const float a = fminf(0.99f, a2.y * g);
        const float alpha = (power > 0.0f || a < ALPHA_MIN) ? 0.0f : a;
        const float test = T * (1.0f - alpha);
        if (test < T_EPS) break;
        const float w = alpha * T;
        cr = fmaf(w, a2.z, cr);
        cg = fmaf(w, a2.w, cg);
        cb = fmaf(w, ccb[j], cb);
        T = test;
    }

    const int pix = (ty0 + ly) * IMG_W + tx0 + lx;
    out_img[0 * NPIX + pix] = cr + bg0 * T;
    out_img[1 * NPIX + pix] = cg + bg1 * T;
    out_img[2 * NPIX + pix] = cb + bg2 * T;
}

extern "C" void kernel_launch(void* const* d_in, const int* in_sizes, int n_in,
                              void* d_out, int out_size) {
    const float* means3D   = (const float*)d_in[0];
    const float* opacities = (const float*)d_in[2];
    const float* colors    = (const float*)d_in[3];
    const float* scales    = (const float*)d_in[4];
    const float* rotations = (const float*)d_in[5];
    const float* bg        = (const float*)d_in[6];
    const float* viewm     = (const float*)d_in[7];
    const float* projm     = (const float*)d_in[8];

    float* out = (float*)d_out;
    float* out_radii = out + 3 * NPIX;

    fused_kernel<<<NTILES, 256>>>(means3D, opacities, colors, scales,
                                  rotations, viewm, projm, bg, out, out_radii);
}